// round 2
// baseline (speedup 1.0000x reference)
#include <cuda_runtime.h>

#define H   192
#define PP  64
#define K2  384
#define TM  128
#define TN  128
#define KC  32
#define LDT 132   // padded tile leading dim

// smem floats: logits region TM*LDT (aliases As/Bs) + bias(128) + pos(192)
#define SMEM_FLOATS (TM*LDT + 128 + 192)

__global__ __launch_bounds__(256, 2)
void taps_kernel(const float* __restrict__ token_state,
                 const float* __restrict__ prev_state,
                 const float* __restrict__ W_sel,
                 const float* __restrict__ b_sel,
                 const float* __restrict__ W_br,
                 const float* __restrict__ b_br,
                 const float* __restrict__ patch_values,
                 const float* __restrict__ patch_positions,
                 float* __restrict__ out_ps,
                 float* __restrict__ out_w,
                 float* __restrict__ out_anchor,
                 float* __restrict__ out_lm,
                 float* __restrict__ out_bm,
                 float* __restrict__ out_md,
                 float* __restrict__ out_rad,
                 float* __restrict__ out_bs,
                 int B)
{
    extern __shared__ float smem[];
    float* As   = smem;                 // [KC][LDT] during GEMM
    float* Bs   = smem + KC * LDT;      // [KC][LDT] during GEMM
    float* Lg   = smem;                 // [TM][LDT] after GEMM (aliases tiles)
    float* bias = smem + TM * LDT;      // 128
    float* posx = bias + 128;           // 64
    float* posy = posx + 64;
    float* posz = posy + 64;

    const int tid = threadIdx.x;
    const int m0  = blockIdx.x * TM;

    if (tid < 64) {
        bias[tid]      = b_sel[tid];
        bias[64 + tid] = b_br[tid];
        posx[tid] = patch_positions[tid * 3 + 0];
        posy[tid] = patch_positions[tid * 3 + 1];
        posz[tid] = patch_positions[tid * 3 + 2];
    }

    const int tx = tid & 15;   // output dim
    const int ty = tid >> 4;   // token dim

    float acc[8][8];
    #pragma unroll
    for (int i = 0; i < 8; i++)
        #pragma unroll
        for (int j = 0; j < 8; j++) acc[i][j] = 0.0f;

    for (int kc = 0; kc < 12; kc++) {
        const float* qsrc  = (kc < 6) ? token_state : prev_state;
        const int    qcol0 = (kc % 6) * KC;

        __syncthreads();  // previous compute done before overwriting tiles
        // ---- load Q tile transposed: As[k][m] ----
        #pragma unroll
        for (int t = 0; t < 4; t++) {
            int idx = tid + t * 256;       // 0..1023
            int m   = idx >> 3;            // 0..127
            int k4  = idx & 7;             // 0..7
            int mg  = m0 + m; if (mg >= B) mg = B - 1;
            float4 v = *reinterpret_cast<const float4*>(qsrc + (size_t)mg * H + qcol0 + k4 * 4);
            int kk = k4 * 4;
            As[(kk + 0) * LDT + m] = v.x;
            As[(kk + 1) * LDT + m] = v.y;
            As[(kk + 2) * LDT + m] = v.z;
            As[(kk + 3) * LDT + m] = v.w;
        }
        // ---- load W tile transposed: Bs[k][n], rows 0..63 = W_sel, 64..127 = W_br ----
        #pragma unroll
        for (int t = 0; t < 4; t++) {
            int idx = tid + t * 256;
            int n   = idx >> 3;
            int k4  = idx & 7;
            const float* wsrc = (n < 64) ? (W_sel + (size_t)n * K2)
                                         : (W_br + (size_t)(n - 64) * K2);
            float4 v = *reinterpret_cast<const float4*>(wsrc + kc * KC + k4 * 4);
            int kk = k4 * 4;
            Bs[(kk + 0) * LDT + n] = v.x;
            Bs[(kk + 1) * LDT + n] = v.y;
            Bs[(kk + 2) * LDT + n] = v.z;
            Bs[(kk + 3) * LDT + n] = v.w;
        }
        __syncthreads();

        #pragma unroll 4
        for (int k = 0; k < KC; k++) {
            float4 a0 = *reinterpret_cast<const float4*>(&As[k * LDT + ty * 8]);
            float4 a1 = *reinterpret_cast<const float4*>(&As[k * LDT + ty * 8 + 4]);
            float4 b0 = *reinterpret_cast<const float4*>(&Bs[k * LDT + tx * 8]);
            float4 b1 = *reinterpret_cast<const float4*>(&Bs[k * LDT + tx * 8 + 4]);
            float a[8] = {a0.x, a0.y, a0.z, a0.w, a1.x, a1.y, a1.z, a1.w};
            float b[8] = {b0.x, b0.y, b0.z, b0.w, b1.x, b1.y, b1.z, b1.w};
            #pragma unroll
            for (int i = 0; i < 8; i++)
                #pragma unroll
                for (int j = 0; j < 8; j++)
                    acc[i][j] = fmaf(a[i], b[j], acc[i][j]);
        }
    }

    __syncthreads();  // all tile reads done before aliasing Lg over As/Bs
    // ---- epilogue: biased logits to smem ----
    #pragma unroll
    for (int i = 0; i < 8; i++) {
        int row = ty * 8 + i;
        #pragma unroll
        for (int j = 0; j < 8; j += 4) {
            float4 v;
            v.x = acc[i][j + 0] + bias[tx * 8 + j + 0];
            v.y = acc[i][j + 1] + bias[tx * 8 + j + 1];
            v.z = acc[i][j + 2] + bias[tx * 8 + j + 2];
            v.w = acc[i][j + 3] + bias[tx * 8 + j + 3];
            *reinterpret_cast<float4*>(&Lg[row * LDT + tx * 8 + j]) = v;
        }
    }
    __syncthreads();

    // ---- postprocess: one warp per token, 16 tokens per warp ----
    const unsigned F = 0xffffffffu;
    const int lane = tid & 31;
    const int wid  = tid >> 5;
    const float PXa = posx[lane],      PYa = posy[lane],      PZa = posz[lane];
    const float PXb = posx[lane + 32], PYb = posy[lane + 32], PZb = posz[lane + 32];
    const float RAD  = 0.42f;
    const float NEGK = -1.0f / (2.0f * 0.42f * 0.42f);

    for (int r = 0; r < 16; r++) {
        int t  = wid * 16 + r;
        int tg = m0 + t;
        if (tg >= B) break;
        const float* L = &Lg[t * LDT];
        float ba = L[lane],      bb = L[lane + 32];
        float ga = L[lane + 64], gb = L[lane + 96];

        // base softmax over 64
        float mx = fmaxf(ba, bb);
        #pragma unroll
        for (int o = 16; o; o >>= 1) mx = fmaxf(mx, __shfl_xor_sync(F, mx, o));
        float ea = expf(ba - mx), eb = expf(bb - mx);
        float s = ea + eb;
        #pragma unroll
        for (int o = 16; o; o >>= 1) s += __shfl_xor_sync(F, s, o);
        float inv = 1.0f / s;
        float wa = ea * inv, wb = eb * inv;

        // anchor position
        float ax = wa * PXa + wb * PXb;
        float ay = wa * PYa + wb * PYb;
        float az = wa * PZa + wb * PZb;
        #pragma unroll
        for (int o = 16; o; o >>= 1) {
            ax += __shfl_xor_sync(F, ax, o);
            ay += __shfl_xor_sync(F, ay, o);
            az += __shfl_xor_sync(F, az, o);
        }

        // distances, kernel, local mask
        float dxa = ax - PXa, dya = ay - PYa, dza = az - PZa;
        float dxb = ax - PXb, dyb = ay - PYb, dzb = az - PZb;
        float da = sqrtf(dxa * dxa + dya * dya + dza * dza);
        float db = sqrtf(dxb * dxb + dyb * dyb + dzb * dzb);
        float ka = expf(da * da * NEGK);
        float kb = expf(db * db * NEGK);
        bool la = (da <= RAD), lb = (db <= RAD);

        // argmin distance (tie -> lowest index, like jnp.argmin)
        unsigned long long keya = (((unsigned long long)__float_as_uint(da)) << 32) | (unsigned)lane;
        unsigned long long keyb = (((unsigned long long)__float_as_uint(db)) << 32) | (unsigned)(lane + 32);
        unsigned long long kmin = keya < keyb ? keya : keyb;
        #pragma unroll
        for (int o = 16; o; o >>= 1) {
            unsigned long long ok = __shfl_xor_sync(F, kmin, o);
            if (ok < kmin) kmin = ok;
        }
        int nearest = (int)(kmin & 0x3fu);
        la = la || (lane == nearest);
        lb = lb || (lane + 32 == nearest);

        // bridge logits masked + iterative top-6 (tie -> lowest index, like lax.top_k)
        float va = la ? -1e9f : ga;
        float vb = lb ? -1e9f : gb;
        float tv[6]; int ti[6];
        #pragma unroll
        for (int j = 0; j < 6; j++) {
            float bv; int bi;
            if (va >= vb) { bv = va; bi = lane; } else { bv = vb; bi = lane + 32; }
            #pragma unroll
            for (int o = 16; o; o >>= 1) {
                float ov = __shfl_xor_sync(F, bv, o);
                int   oi = __shfl_xor_sync(F, bi, o);
                if (ov > bv || (ov == bv && oi < bi)) { bv = ov; bi = oi; }
            }
            tv[j] = bv; ti[j] = bi;
            if (bi == lane)      va = -3.4e38f;
            if (bi == lane + 32) vb = -3.4e38f;
        }
        // top-k softmax (tv[0] is the max: values descend)
        float s6 = 0.0f, e6[6];
        #pragma unroll
        for (int j = 0; j < 6; j++) { e6[j] = expf(tv[j] - tv[0]); s6 += e6[j]; }
        float is6 = 1.0f / s6;
        float sba = 0.0f, sbb = 0.0f;
        #pragma unroll
        for (int j = 0; j < 6; j++) {
            float v = e6[j] * is6;
            if (ti[j] == lane)      sba = v;
            if (ti[j] == lane + 32) sbb = v;
        }

        float fla = la ? 1.0f : 0.0f, flb = lb ? 1.0f : 0.0f;
        float ma = wa * ka * fla + 0.18f * sba;
        float mb = wb * kb * flb + 0.18f * sbb;
        float sm = ma + mb;
        #pragma unroll
        for (int o = 16; o; o >>= 1) sm += __shfl_xor_sync(F, sm, o);
        float invd = 1.0f / fmaxf(sm, 1e-6f);
        float Wa = ma * invd, Wb = mb * invd;

        out_w[(size_t)tg * PP + lane]      = Wa;
        out_w[(size_t)tg * PP + 32 + lane] = Wb;

        float lm = Wa * fla + Wb * flb;
        float bm = Wa * (1.0f - fla) + Wb * (1.0f - flb);
        float md = Wa * da + Wb * db;
        #pragma unroll
        for (int o = 16; o; o >>= 1) {
            lm += __shfl_xor_sync(F, lm, o);
            bm += __shfl_xor_sync(F, bm, o);
            md += __shfl_xor_sync(F, md, o);
        }

        // sparse patch_state: weights have <= ~8 nonzeros
        float pacc[6] = {0, 0, 0, 0, 0, 0};
        unsigned bal0 = __ballot_sync(F, Wa != 0.0f);
        unsigned bal1 = __ballot_sync(F, Wb != 0.0f);
        while (bal0) {
            int p = __ffs(bal0) - 1; bal0 &= bal0 - 1;
            float wv = __shfl_sync(F, Wa, p);
            const float* row = patch_values + p * H;
            #pragma unroll
            for (int j = 0; j < 6; j++) pacc[j] += wv * __ldg(row + lane + 32 * j);
        }
        while (bal1) {
            int p = __ffs(bal1) - 1; bal1 &= bal1 - 1;
            float wv = __shfl_sync(F, Wb, p);
            const float* row = patch_values + (p + 32) * H;
            #pragma unroll
            for (int j = 0; j < 6; j++) pacc[j] += wv * __ldg(row + lane + 32 * j);
        }
        #pragma unroll
        for (int j = 0; j < 6; j++) out_ps[(size_t)tg * H + lane + 32 * j] = pacc[j];

        if (lane == 0) {
            out_anchor[(size_t)tg * 3 + 0] = ax;
            out_anchor[(size_t)tg * 3 + 1] = ay;
            out_anchor[(size_t)tg * 3 + 2] = az;
            out_lm[tg]  = lm;
            out_bm[tg]  = bm;
            out_md[tg]  = md;
            out_rad[tg] = RAD;
            out_bs[tg]  = 0.18f;
        }
    }
}

extern "C" void kernel_launch(void* const* d_in, const int* in_sizes, int n_in,
                              void* d_out, int out_size)
{
    const float* token_state     = (const float*)d_in[0];
    const float* prev_state      = (const float*)d_in[1];
    const float* W_sel           = (const float*)d_in[2];
    const float* b_sel           = (const float*)d_in[3];
    const float* W_br            = (const float*)d_in[4];
    const float* b_br            = (const float*)d_in[5];
    const float* patch_values    = (const float*)d_in[6];
    const float* patch_positions = (const float*)d_in[7];

    const int B = in_sizes[0] / H;
    float* o = (float*)d_out;
    float* out_ps     = o;                              // [B,192]
    float* out_w      = o + (size_t)B * H;              // [B,64]
    float* out_anchor = o + (size_t)B * (H + PP);       // [B,3]
    float* out_lm     = o + (size_t)B * (H + PP + 3);   // [B,1]
    float* out_bm     = out_lm + B;
    float* out_md     = out_bm + B;
    float* out_rad    = out_md + B;
    float* out_bs     = out_rad + B;

    const int smem_bytes = SMEM_FLOATS * sizeof(float); // 68864 B
    cudaFuncSetAttribute(taps_kernel, cudaFuncAttributeMaxDynamicSharedMemorySize, smem_bytes);

    int grid = (B + TM - 1) / TM;
    taps_kernel<<<grid, 256, smem_bytes>>>(
        token_state, prev_state, W_sel, b_sel, W_br, b_br,
        patch_values, patch_positions,
        out_ps, out_w, out_anchor, out_lm, out_bm, out_md, out_rad, out_bs, B);
}